// round 2
// baseline (speedup 1.0000x reference)
#include <cuda_runtime.h>

#define ALPHA 0.2f
#define MAXN 50048

// ---------------- device scratch (no allocation allowed) ----------------
__device__ float g_wself[128];
__device__ float g_wneigh[128];
__device__ float g_bufA[MAXN * 128];
__device__ float g_bufB[MAXN * 128];
__device__ float g_sum[384];   // per-layer column sums   (3 x 128)
__device__ float g_sq[384];    // per-layer column sumsq  (3 x 128)
__device__ float g_ca[384];    // per-layer BN scale a = gamma * rsqrt(var+eps)
__device__ float g_cc[384];    // per-layer BN shift c = beta - a*mean

__device__ __forceinline__ float leaky(float x) { return fmaxf(x, ALPHA * x); }

__device__ __forceinline__ float warp_sum(float v) {
#pragma unroll
    for (int o = 16; o > 0; o >>= 1) v += __shfl_xor_sync(0xffffffffu, v, o);
    return v;
}

// ---------------- prep: w_self = W_t @ a_self, w_neigh = W_t @ a_neigh; zero stats ----
__global__ void prep_kernel(const float* __restrict__ Wt, const float* __restrict__ a_att) {
    int d = threadIdx.x;
    if (d < 128) {
        float s1 = 0.f, s2 = 0.f;
#pragma unroll 8
        for (int t = 0; t < 128; t++) {
            float w = Wt[d * 128 + t];
            s1 += w * a_att[t];
            s2 += w * a_att[128 + t];
        }
        g_wself[d] = s1;
        g_wneigh[d] = s2;
    }
    for (int i = threadIdx.x; i < 384; i += blockDim.x) {
        g_sum[i] = 0.f;
        g_sq[i] = 0.f;
    }
}

// ---------------- attention + aggregate + fused x@W_t -------------------
// One warp handles 2 nodes. Online softmax over K=25 neighbors, each neighbor
// row (512B) read exactly once, fully coalesced (lane l owns dims 4l..4l+3).
// Then block-staged W_t (two 32KB halves) does y = x @ W_t from smem.
__global__ void attn_kernel(const float* __restrict__ selfv,
                            const float* __restrict__ neigh,
                            const float* __restrict__ Wt,
                            const float* __restrict__ eps_p,
                            float* __restrict__ Y0, int N) {
    __shared__ float Wts[64 * 128];   // 32KB: half of W_t
    __shared__ float xrow[16 * 128];  // 8KB: aggregated x per node

    int tid = threadIdx.x;
    int w = tid >> 5;
    int l = tid & 31;

    float onepe = 1.0f + eps_p[0];
    float4 ws4 = ((const float4*)g_wself)[l];
    float4 wn4 = ((const float4*)g_wneigh)[l];

    int n0 = blockIdx.x * 16 + w * 2;

#pragma unroll
    for (int node = 0; node < 2; node++) {
        int n = n0 + node;
        int nn = (n < N) ? n : (N - 1);  // clamp; results for invalid nodes discarded

        float4 sv = ((const float4*)(selfv + (long)nn * 128))[l];
        float ss = warp_sum(sv.x * ws4.x + sv.y * ws4.y + sv.z * ws4.z + sv.w * ws4.w);

        const float4* nb = (const float4*)(neigh + (long)nn * 3200);
        float m = -1e30f, Z = 0.f;
        float4 acc = make_float4(0.f, 0.f, 0.f, 0.f);

        for (int k = 0; k < 25; k++) {
            float4 v = nb[k * 32 + l];
            float s = warp_sum(v.x * wn4.x + v.y * wn4.y + v.z * wn4.z + v.w * wn4.w) + ss;
            s = leaky(s);
            if (s <= m) {  // warp-uniform branch (s, m uniform after reduction)
                float p = __expf(s - m);
                Z += p;
                acc.x += p * v.x; acc.y += p * v.y; acc.z += p * v.z; acc.w += p * v.w;
            } else {
                float sc = __expf(m - s);
                Z = Z * sc + 1.f;
                acc.x = acc.x * sc + v.x; acc.y = acc.y * sc + v.y;
                acc.z = acc.z * sc + v.z; acc.w = acc.w * sc + v.w;
                m = s;
            }
        }
        float inv = 1.f / Z;
        float4 x;
        x.x = onepe * sv.x + acc.x * inv;
        x.y = onepe * sv.y + acc.y * inv;
        x.z = onepe * sv.z + acc.z * inv;
        x.w = onepe * sv.w + acc.w * inv;
        ((float4*)(xrow + (w * 2 + node) * 128))[l] = x;
    }
    __syncwarp();

    float4 ya = make_float4(0.f, 0.f, 0.f, 0.f);
    float4 yb = make_float4(0.f, 0.f, 0.f, 0.f);
    const float4* xa = (const float4*)(xrow + w * 256);
    const float4* xb = xa + 32;

#pragma unroll 1
    for (int half = 0; half < 2; half++) {
        // cooperative load of W_t rows [half*64, half*64+64)
#pragma unroll
        for (int it = 0; it < 8; it++) {
            int fi = tid + it * 256;  // 0..2047 float4s
            ((float4*)Wts)[fi] = ((const float4*)(Wt + half * 8192))[fi];
        }
        __syncthreads();
#pragma unroll
        for (int s = 0; s < 16; s++) {
            float4 A = xa[half * 16 + s];  // broadcast within warp
            float4 B = xb[half * 16 + s];
            float4 W0 = ((const float4*)(Wts + (4 * s + 0) * 128))[l];
            float4 W1 = ((const float4*)(Wts + (4 * s + 1) * 128))[l];
            float4 W2 = ((const float4*)(Wts + (4 * s + 2) * 128))[l];
            float4 W3 = ((const float4*)(Wts + (4 * s + 3) * 128))[l];
            ya.x += A.x * W0.x + A.y * W1.x + A.z * W2.x + A.w * W3.x;
            ya.y += A.x * W0.y + A.y * W1.y + A.z * W2.y + A.w * W3.y;
            ya.z += A.x * W0.z + A.y * W1.z + A.z * W2.z + A.w * W3.z;
            ya.w += A.x * W0.w + A.y * W1.w + A.z * W2.w + A.w * W3.w;
            yb.x += B.x * W0.x + B.y * W1.x + B.z * W2.x + B.w * W3.x;
            yb.y += B.x * W0.y + B.y * W1.y + B.z * W2.y + B.w * W3.y;
            yb.z += B.x * W0.z + B.y * W1.z + B.z * W2.z + B.w * W3.z;
            yb.w += B.x * W0.w + B.y * W1.w + B.z * W2.w + B.w * W3.w;
        }
        __syncthreads();
    }

    if (n0 < N)     ((float4*)(Y0 + (long)n0 * 128))[l] = ya;
    if (n0 + 1 < N) ((float4*)(Y0 + (long)(n0 + 1) * 128))[l] = yb;
}

// ---------------- GEMM: Y = f(X) @ W + bias, accumulate BN stats --------
// f(x) = leaky(ain[k]*x + cin[k]) if HAS_IN (previous layer's BN+act fused
// into the load), else identity. 128x128 tile, 256 threads, 8x8 microtile.
template <bool HAS_IN>
__global__ void __launch_bounds__(256)
gemm_kernel(const float* __restrict__ X, const float* __restrict__ W,
            const float* __restrict__ bias,
            const float* __restrict__ ain, const float* __restrict__ cin,
            float* __restrict__ Y, float* __restrict__ psum,
            float* __restrict__ psq, int N) {
    __shared__ float Ws[16][128];
    __shared__ float Xs[16][132];
    __shared__ float reds[16][128];
    __shared__ float redq[16][128];

    int tid = threadIdx.x;
    int tx = tid & 15, ty = tid >> 4;
    int row0 = blockIdx.x << 7;

    float acc[8][8];
#pragma unroll
    for (int i = 0; i < 8; i++)
#pragma unroll
        for (int j = 0; j < 8; j++) acc[i][j] = 0.f;

#pragma unroll 1
    for (int k0 = 0; k0 < 128; k0 += 16) {
        // stage W chunk [k0..k0+15][0..127]
#pragma unroll
        for (int it = 0; it < 2; it++) {
            int fi = tid + (it << 8);
            int kk = fi >> 5, cc = fi & 31;
            *((float4*)&Ws[kk][cc << 2]) = ((const float4*)(W + (k0 + kk) * 128))[cc];
        }
        // stage X chunk, transposed, with optional fused BN+leaky
#pragma unroll
        for (int it = 0; it < 2; it++) {
            int fi = tid + (it << 8);
            int r = fi >> 2, q = fi & 3;
            int gr = row0 + r;
            float4 v = make_float4(0.f, 0.f, 0.f, 0.f);
            if (gr < N) v = ((const float4*)(X + (long)gr * 128 + k0))[q];
            if (HAS_IN) {
                int kk = k0 + (q << 2);
                float t;
                t = ain[kk + 0] * v.x + cin[kk + 0]; v.x = leaky(t);
                t = ain[kk + 1] * v.y + cin[kk + 1]; v.y = leaky(t);
                t = ain[kk + 2] * v.z + cin[kk + 2]; v.z = leaky(t);
                t = ain[kk + 3] * v.w + cin[kk + 3]; v.w = leaky(t);
            }
            Xs[(q << 2) + 0][r] = v.x;
            Xs[(q << 2) + 1][r] = v.y;
            Xs[(q << 2) + 2][r] = v.z;
            Xs[(q << 2) + 3][r] = v.w;
        }
        __syncthreads();
#pragma unroll
        for (int k = 0; k < 16; k++) {
            float4 a0 = *(const float4*)&Xs[k][ty << 2];
            float4 a1 = *(const float4*)&Xs[k][64 + (ty << 2)];
            float4 b0 = *(const float4*)&Ws[k][tx << 2];
            float4 b1 = *(const float4*)&Ws[k][64 + (tx << 2)];
            float a[8] = {a0.x, a0.y, a0.z, a0.w, a1.x, a1.y, a1.z, a1.w};
            float b[8] = {b0.x, b0.y, b0.z, b0.w, b1.x, b1.y, b1.z, b1.w};
#pragma unroll
            for (int i = 0; i < 8; i++)
#pragma unroll
                for (int j = 0; j < 8; j++) acc[i][j] += a[i] * b[j];
        }
        __syncthreads();
    }

    int cols0 = tx << 2;
    float bv[8];
#pragma unroll
    for (int j = 0; j < 4; j++) {
        bv[j] = bias[cols0 + j];
        bv[4 + j] = bias[64 + cols0 + j];
    }
#pragma unroll
    for (int i = 0; i < 8; i++)
#pragma unroll
        for (int j = 0; j < 8; j++) acc[i][j] += bv[j];

    // per-thread column partials (row-masked), tree reduce in smem
#pragma unroll
    for (int j = 0; j < 8; j++) {
        float s = 0.f, q = 0.f;
#pragma unroll
        for (int i = 0; i < 8; i++) {
            int rr = (i < 4) ? ((ty << 2) + i) : (64 + (ty << 2) + i - 4);
            if (row0 + rr < N) {
                float y = acc[i][j];
                s += y;
                q += y * y;
            }
        }
        int col = (j < 4) ? (cols0 + j) : (64 + cols0 + j - 4);
        reds[ty][col] = s;
        redq[ty][col] = q;
    }
    __syncthreads();
    if (tid < 128) {
        float s = 0.f, q = 0.f;
#pragma unroll
        for (int t = 0; t < 16; t++) {
            s += reds[t][tid];
            q += redq[t][tid];
        }
        atomicAdd(&psum[tid], s);
        atomicAdd(&psq[tid], q);
    }

    // store raw (pre-BN) outputs, float4-coalesced
#pragma unroll
    for (int i = 0; i < 8; i++) {
        int rr = (i < 4) ? ((ty << 2) + i) : (64 + (ty << 2) + i - 4);
        int gr = row0 + rr;
        if (gr < N) {
            float4 o0 = make_float4(acc[i][0], acc[i][1], acc[i][2], acc[i][3]);
            float4 o1 = make_float4(acc[i][4], acc[i][5], acc[i][6], acc[i][7]);
            *((float4*)(Y + (long)gr * 128 + cols0)) = o0;
            *((float4*)(Y + (long)gr * 128 + 64 + cols0)) = o1;
        }
    }
}

// ---------------- finalize BN coefficients ------------------------------
__global__ void finalize_kernel(const float* __restrict__ s, const float* __restrict__ q,
                                const float* __restrict__ gam, const float* __restrict__ bet,
                                float* __restrict__ a, float* __restrict__ c, int N) {
    int j = threadIdx.x;
    float invN = 1.0f / (float)N;
    float mean = s[j] * invN;
    float var = fmaxf(q[j] * invN - mean * mean, 0.f);
    float rs = rsqrtf(var + 1e-5f);
    float aj = gam[j] * rs;
    a[j] = aj;
    c[j] = bet[j] - aj * mean;
}

// ---------------- final BN + leaky on layer-3 output (in place) ---------
__global__ void epilogue_kernel(float* __restrict__ Y, const float* __restrict__ a,
                                const float* __restrict__ c, int n4) {
    int i = blockIdx.x * blockDim.x + threadIdx.x;
    if (i < n4) {
        float4 v = ((const float4*)Y)[i];
        int cb = (i & 31) << 2;
        float t;
        t = a[cb + 0] * v.x + c[cb + 0]; v.x = leaky(t);
        t = a[cb + 1] * v.y + c[cb + 1]; v.y = leaky(t);
        t = a[cb + 2] * v.z + c[cb + 2]; v.z = leaky(t);
        t = a[cb + 3] * v.w + c[cb + 3]; v.w = leaky(t);
        ((float4*)Y)[i] = v;
    }
}

// ---------------- launch -------------------------------------------------
extern "C" void kernel_launch(void* const* d_in, const int* in_sizes, int n_in,
                              void* d_out, int out_size) {
    const float* selfv = (const float*)d_in[0];
    const float* neigh = (const float*)d_in[1];
    const float* Wt    = (const float*)d_in[2];
    const float* aatt  = (const float*)d_in[3];
    const float* eps   = (const float*)d_in[4];
    const float* W1 = (const float*)d_in[5];
    const float* b1 = (const float*)d_in[6];
    const float* g1 = (const float*)d_in[7];
    const float* be1 = (const float*)d_in[8];
    const float* W2 = (const float*)d_in[9];
    const float* b2 = (const float*)d_in[10];
    const float* g2 = (const float*)d_in[11];
    const float* be2 = (const float*)d_in[12];
    const float* W3 = (const float*)d_in[13];
    const float* b3 = (const float*)d_in[14];
    const float* g3 = (const float*)d_in[15];
    const float* be3 = (const float*)d_in[16];
    float* out = (float*)d_out;

    int N = in_sizes[0] / 128;

    float *bufA = nullptr, *bufB = nullptr, *sum = nullptr, *sq = nullptr,
          *ca = nullptr, *cc = nullptr;
    cudaGetSymbolAddress((void**)&bufA, g_bufA);
    cudaGetSymbolAddress((void**)&bufB, g_bufB);
    cudaGetSymbolAddress((void**)&sum, g_sum);
    cudaGetSymbolAddress((void**)&sq, g_sq);
    cudaGetSymbolAddress((void**)&ca, g_ca);
    cudaGetSymbolAddress((void**)&cc, g_cc);

    prep_kernel<<<1, 256>>>(Wt, aatt);
    attn_kernel<<<(N + 15) / 16, 256>>>(selfv, neigh, Wt, eps, bufA, N);

    int gg = (N + 127) / 128;
    gemm_kernel<false><<<gg, 256>>>(bufA, W1, b1, nullptr, nullptr, bufB, sum + 0, sq + 0, N);
    finalize_kernel<<<1, 128>>>(sum + 0, sq + 0, g1, be1, ca + 0, cc + 0, N);
    gemm_kernel<true><<<gg, 256>>>(bufB, W2, b2, ca + 0, cc + 0, bufA, sum + 128, sq + 128, N);
    finalize_kernel<<<1, 128>>>(sum + 128, sq + 128, g2, be2, ca + 128, cc + 128, N);
    gemm_kernel<true><<<gg, 256>>>(bufA, W3, b3, ca + 128, cc + 128, out, sum + 256, sq + 256, N);
    finalize_kernel<<<1, 128>>>(sum + 256, sq + 256, g3, be3, ca + 256, cc + 256, N);

    int n4 = N * 32;
    epilogue_kernel<<<(n4 + 255) / 256, 256>>>(out, ca + 256, cc + 256, n4);
}

// round 4
// speedup vs baseline: 1.1275x; 1.1275x over previous
#include <cuda_runtime.h>
#include <cuda_bf16.h>
#include <cstdint>

#define ALPHA 0.2f
#define MAXN 50048

// ---------------- device scratch ----------------
__device__ float g_wself[128];
__device__ float g_wneigh[128];
__device__ float g_bufA[MAXN * 128];
__device__ float g_bufB[MAXN * 128];
__device__ float g_sum[384];
__device__ float g_sq[384];
__device__ float g_ca[384];
__device__ float g_cc[384];
__device__ __nv_bfloat16 g_bthi[3 * 16384];  // W^T hi, 3 layers, [n][k] row-major
__device__ __nv_bfloat16 g_btlo[3 * 16384];  // W^T lo

__device__ __forceinline__ float leaky(float x) { return fmaxf(x, ALPHA * x); }

__device__ __forceinline__ float warp_sum(float v) {
#pragma unroll
    for (int o = 16; o > 0; o >>= 1) v += __shfl_xor_sync(0xffffffffu, v, o);
    return v;
}

// ---------------- prep: attention vectors + zero stats ----------------
__global__ void prep_kernel(const float* __restrict__ Wt, const float* __restrict__ a_att) {
    int d = threadIdx.x;
    if (d < 128) {
        float s1 = 0.f, s2 = 0.f;
#pragma unroll 8
        for (int t = 0; t < 128; t++) {
            float w = Wt[d * 128 + t];
            s1 += w * a_att[t];
            s2 += w * a_att[128 + t];
        }
        g_wself[d] = s1;
        g_wneigh[d] = s2;
    }
    for (int i = threadIdx.x; i < 384; i += blockDim.x) {
        g_sum[i] = 0.f;
        g_sq[i] = 0.f;
    }
}

// ---------------- transpose + hi/lo split of the 3 weight matrices ----------------
__global__ void transpose_kernel(const float* __restrict__ W1, const float* __restrict__ W2,
                                 const float* __restrict__ W3,
                                 __nv_bfloat16* __restrict__ bthi,
                                 __nv_bfloat16* __restrict__ btlo) {
    __shared__ float tile[32][33];
    const float* W = (blockIdx.x == 0) ? W1 : (blockIdx.x == 1) ? W2 : W3;
    __nv_bfloat16* oh = bthi + blockIdx.x * 16384;
    __nv_bfloat16* ol = btlo + blockIdx.x * 16384;
    int tx = threadIdx.x & 31, ty = threadIdx.x >> 5;  // 32 x 8
    for (int ti = 0; ti < 4; ti++)
        for (int tj = 0; tj < 4; tj++) {
            __syncthreads();
#pragma unroll
            for (int it = 0; it < 4; it++)
                tile[ty + 8 * it][tx] = W[(ti * 32 + ty + 8 * it) * 128 + tj * 32 + tx];
            __syncthreads();
#pragma unroll
            for (int it = 0; it < 4; it++) {
                int n = tj * 32 + ty + 8 * it, k = ti * 32 + tx;
                float v = tile[tx][ty + 8 * it];
                __nv_bfloat16 h = __float2bfloat16(v);
                oh[n * 128 + k] = h;
                ol[n * 128 + k] = __float2bfloat16(v - __bfloat162float(h));
            }
        }
}

// ---------------- attention + aggregate + fused x@W_t (unchanged) ----------------
__global__ void attn_kernel(const float* __restrict__ selfv,
                            const float* __restrict__ neigh,
                            const float* __restrict__ Wt,
                            const float* __restrict__ eps_p,
                            float* __restrict__ Y0, int N) {
    __shared__ float Wts[64 * 128];
    __shared__ float xrow[16 * 128];

    int tid = threadIdx.x;
    int w = tid >> 5;
    int l = tid & 31;

    float onepe = 1.0f + eps_p[0];
    float4 ws4 = ((const float4*)g_wself)[l];
    float4 wn4 = ((const float4*)g_wneigh)[l];

    int n0 = blockIdx.x * 16 + w * 2;

#pragma unroll
    for (int node = 0; node < 2; node++) {
        int n = n0 + node;
        int nn = (n < N) ? n : (N - 1);

        float4 sv = ((const float4*)(selfv + (long)nn * 128))[l];
        float ss = warp_sum(sv.x * ws4.x + sv.y * ws4.y + sv.z * ws4.z + sv.w * ws4.w);

        const float4* nb = (const float4*)(neigh + (long)nn * 3200);
        float m = -1e30f, Z = 0.f;
        float4 acc = make_float4(0.f, 0.f, 0.f, 0.f);

        for (int k = 0; k < 25; k++) {
            float4 v = nb[k * 32 + l];
            float s = warp_sum(v.x * wn4.x + v.y * wn4.y + v.z * wn4.z + v.w * wn4.w) + ss;
            s = leaky(s);
            if (s <= m) {
                float p = __expf(s - m);
                Z += p;
                acc.x += p * v.x; acc.y += p * v.y; acc.z += p * v.z; acc.w += p * v.w;
            } else {
                float sc = __expf(m - s);
                Z = Z * sc + 1.f;
                acc.x = acc.x * sc + v.x; acc.y = acc.y * sc + v.y;
                acc.z = acc.z * sc + v.z; acc.w = acc.w * sc + v.w;
                m = s;
            }
        }
        float inv = 1.f / Z;
        float4 x;
        x.x = onepe * sv.x + acc.x * inv;
        x.y = onepe * sv.y + acc.y * inv;
        x.z = onepe * sv.z + acc.z * inv;
        x.w = onepe * sv.w + acc.w * inv;
        ((float4*)(xrow + (w * 2 + node) * 128))[l] = x;
    }
    __syncwarp();

    float4 ya = make_float4(0.f, 0.f, 0.f, 0.f);
    float4 yb = make_float4(0.f, 0.f, 0.f, 0.f);
    const float4* xa = (const float4*)(xrow + w * 256);
    const float4* xb = xa + 32;

#pragma unroll 1
    for (int half = 0; half < 2; half++) {
#pragma unroll
        for (int it = 0; it < 8; it++) {
            int fi = tid + it * 256;
            ((float4*)Wts)[fi] = ((const float4*)(Wt + half * 8192))[fi];
        }
        __syncthreads();
#pragma unroll
        for (int s = 0; s < 16; s++) {
            float4 A = xa[half * 16 + s];
            float4 B = xb[half * 16 + s];
            float4 W0 = ((const float4*)(Wts + (4 * s + 0) * 128))[l];
            float4 W1 = ((const float4*)(Wts + (4 * s + 1) * 128))[l];
            float4 W2 = ((const float4*)(Wts + (4 * s + 2) * 128))[l];
            float4 W3 = ((const float4*)(Wts + (4 * s + 3) * 128))[l];
            ya.x += A.x * W0.x + A.y * W1.x + A.z * W2.x + A.w * W3.x;
            ya.y += A.x * W0.y + A.y * W1.y + A.z * W2.y + A.w * W3.y;
            ya.z += A.x * W0.z + A.y * W1.z + A.z * W2.z + A.w * W3.z;
            ya.w += A.x * W0.w + A.y * W1.w + A.z * W2.w + A.w * W3.w;
            yb.x += B.x * W0.x + B.y * W1.x + B.z * W2.x + B.w * W3.x;
            yb.y += B.x * W0.y + B.y * W1.y + B.z * W2.y + B.w * W3.y;
            yb.z += B.x * W0.z + B.y * W1.z + B.z * W2.z + B.w * W3.z;
            yb.w += B.x * W0.w + B.y * W1.w + B.z * W2.w + B.w * W3.w;
        }
        __syncthreads();
    }

    if (n0 < N)     ((float4*)(Y0 + (long)n0 * 128))[l] = ya;
    if (n0 + 1 < N) ((float4*)(Y0 + (long)(n0 + 1) * 128))[l] = yb;
}

// ---------------- mma.sync GEMM: Y = f(X) @ W + bias, fused BN stats ----------------
// bf16 hi/lo split, 3 passes: Ahi*Bhi + Ahi*Blo + Alo*Bhi.
// Smem A/B panels use a 272-byte row stride -> conflict-free ldmatrix-less frag loads.
#define A_STRIDE 272
#define SM_BIAS 0
#define SM_CSUM 512
#define SM_CSQ  1024
#define SM_AHI  1536
#define SM_ALO  (SM_AHI + 128 * A_STRIDE)
#define SM_BHI  (SM_ALO + 128 * A_STRIDE)
#define SM_BLO  (SM_BHI + 128 * A_STRIDE)
#define SM_TOTAL (SM_BLO + 128 * A_STRIDE)

__device__ __forceinline__ void mma16816(float* c, uint32_t a0, uint32_t a1, uint32_t a2,
                                         uint32_t a3, uint32_t b0, uint32_t b1) {
    asm volatile(
        "mma.sync.aligned.m16n8k16.row.col.f32.bf16.bf16.f32 "
        "{%0,%1,%2,%3}, {%4,%5,%6,%7}, {%8,%9}, {%0,%1,%2,%3};\n"
        : "+f"(c[0]), "+f"(c[1]), "+f"(c[2]), "+f"(c[3])
        : "r"(a0), "r"(a1), "r"(a2), "r"(a3), "r"(b0), "r"(b1));
}

template <bool HAS_IN>
__global__ void __launch_bounds__(256, 1)
gemm_mma(const float* __restrict__ X, const __nv_bfloat16* __restrict__ bthi,
         const __nv_bfloat16* __restrict__ btlo, const float* __restrict__ bias,
         const float* __restrict__ ain, const float* __restrict__ cin,
         float* __restrict__ Y, float* __restrict__ psum, float* __restrict__ psq,
         int N) {
    extern __shared__ char smem[];
    int tid = threadIdx.x;
    int wid = tid >> 5, lane = tid & 31;
    int wm = wid >> 2, wn = wid & 3;   // warp grid 2 (m) x 4 (n)
    int g = lane >> 2, t = lane & 3;
    int row0 = blockIdx.x << 7;

    if (tid < 128) {
        ((float*)(smem + SM_BIAS))[tid] = bias[tid];
        ((float*)(smem + SM_CSUM))[tid] = 0.f;
        ((float*)(smem + SM_CSQ))[tid] = 0.f;
    }

    // ---- stage A: 128 rows x 128 cols fp32 -> bf16 hi/lo, row stride 272B ----
#pragma unroll
    for (int it = 0; it < 16; it++) {
        int fi = tid + (it << 8);
        int r = fi >> 5, q = fi & 31;  // q = float4 index (4 k-values)
        int gr = row0 + r;
        float4 v = make_float4(0.f, 0.f, 0.f, 0.f);
        if (gr < N) v = ((const float4*)X)[gr * 32 + q];
        if (HAS_IN) {
            int kk = q << 2;
            float tt;
            tt = ain[kk + 0] * v.x + cin[kk + 0]; v.x = leaky(tt);
            tt = ain[kk + 1] * v.y + cin[kk + 1]; v.y = leaky(tt);
            tt = ain[kk + 2] * v.z + cin[kk + 2]; v.z = leaky(tt);
            tt = ain[kk + 3] * v.w + cin[kk + 3]; v.w = leaky(tt);
        }
        __nv_bfloat162 h01, h23, l01, l23;
        h01.x = __float2bfloat16(v.x); h01.y = __float2bfloat16(v.y);
        h23.x = __float2bfloat16(v.z); h23.y = __float2bfloat16(v.w);
        l01.x = __float2bfloat16(v.x - __bfloat162float(h01.x));
        l01.y = __float2bfloat16(v.y - __bfloat162float(h01.y));
        l23.x = __float2bfloat16(v.z - __bfloat162float(h23.x));
        l23.y = __float2bfloat16(v.w - __bfloat162float(h23.y));
        int off = r * A_STRIDE + (q << 3);
        *(__nv_bfloat162*)(smem + SM_AHI + off) = h01;
        *(__nv_bfloat162*)(smem + SM_AHI + off + 4) = h23;
        *(__nv_bfloat162*)(smem + SM_ALO + off) = l01;
        *(__nv_bfloat162*)(smem + SM_ALO + off + 4) = l23;
    }

    // ---- stage B: precomputed W^T hi/lo (bf16, [n][k] 128-wide) -> 272B stride ----
#pragma unroll
    for (int it = 0; it < 8; it++) {
        int fi = tid + (it << 8);
        int n = fi >> 4, c = fi & 15;  // c = uint4 chunk (8 bf16)
        uint4 vh = ((const uint4*)bthi)[fi];
        uint4 vl = ((const uint4*)btlo)[fi];
        int off = n * A_STRIDE + (c << 4);
        *(uint4*)(smem + SM_BHI + off) = vh;
        *(uint4*)(smem + SM_BLO + off) = vl;
    }
    __syncthreads();

    // ---- MMA mainloop ----
    float acc[4][4][4];
#pragma unroll
    for (int mt = 0; mt < 4; mt++)
#pragma unroll
        for (int nt = 0; nt < 4; nt++)
#pragma unroll
            for (int j = 0; j < 4; j++) acc[mt][nt][j] = 0.f;

    const int abase0 = (wm * 64 + g) * A_STRIDE + t * 4;
    const int bbase0 = (wn * 32 + g) * A_STRIDE + t * 4;

#pragma unroll 1
    for (int s = 0; s < 3; s++) {
        const char* Ap = smem + (s == 2 ? SM_ALO : SM_AHI) + abase0;
        const char* Bp = smem + (s == 1 ? SM_BLO : SM_BHI) + bbase0;
#pragma unroll
        for (int ks = 0; ks < 8; ks++) {
            uint32_t a0[4], a1[4], a2[4], a3[4], b0[4], b1[4];
#pragma unroll
            for (int mt = 0; mt < 4; mt++) {
                const char* p = Ap + mt * 16 * A_STRIDE + ks * 32;
                a0[mt] = *(const uint32_t*)(p);
                a1[mt] = *(const uint32_t*)(p + 8 * A_STRIDE);
                a2[mt] = *(const uint32_t*)(p + 16);
                a3[mt] = *(const uint32_t*)(p + 8 * A_STRIDE + 16);
            }
#pragma unroll
            for (int nt = 0; nt < 4; nt++) {
                const char* p = Bp + nt * 8 * A_STRIDE + ks * 32;
                b0[nt] = *(const uint32_t*)(p);
                b1[nt] = *(const uint32_t*)(p + 16);
            }
#pragma unroll
            for (int mt = 0; mt < 4; mt++)
#pragma unroll
                for (int nt = 0; nt < 4; nt++)
                    mma16816(acc[mt][nt], a0[mt], a1[mt], a2[mt], a3[mt], b0[nt], b1[nt]);
        }
    }

    // ---- epilogue: bias, store, fused BN stats ----
    float scol[8], qcol[8];
#pragma unroll
    for (int j = 0; j < 8; j++) { scol[j] = 0.f; qcol[j] = 0.f; }

    const float* bs = (const float*)(smem + SM_BIAS);
#pragma unroll
    for (int nt = 0; nt < 4; nt++) {
        int col = wn * 32 + nt * 8 + 2 * t;
        float bv0 = bs[col], bv1 = bs[col + 1];
#pragma unroll
        for (int mt = 0; mt < 4; mt++) {
            int row = row0 + wm * 64 + mt * 16 + g;
            float c0 = acc[mt][nt][0] + bv0;
            float c1 = acc[mt][nt][1] + bv1;
            float c2 = acc[mt][nt][2] + bv0;
            float c3 = acc[mt][nt][3] + bv1;
            if (row < N) {
                *(float2*)(Y + (long)row * 128 + col) = make_float2(c0, c1);
                scol[nt * 2 + 0] += c0; qcol[nt * 2 + 0] += c0 * c0;
                scol[nt * 2 + 1] += c1; qcol[nt * 2 + 1] += c1 * c1;
            }
            if (row + 8 < N) {
                *(float2*)(Y + (long)(row + 8) * 128 + col) = make_float2(c2, c3);
                scol[nt * 2 + 0] += c2; qcol[nt * 2 + 0] += c2 * c2;
                scol[nt * 2 + 1] += c3; qcol[nt * 2 + 1] += c3 * c3;
            }
        }
    }
    // reduce over groupID lanes (bits 2..4 of lane id)
#pragma unroll
    for (int j = 0; j < 8; j++) {
#pragma unroll
        for (int o = 4; o < 32; o <<= 1) {
            scol[j] += __shfl_xor_sync(0xffffffffu, scol[j], o);
            qcol[j] += __shfl_xor_sync(0xffffffffu, qcol[j], o);
        }
    }
    if (g == 0) {
        float* cs = (float*)(smem + SM_CSUM);
        float* cq = (float*)(smem + SM_CSQ);
#pragma unroll
        for (int nt = 0; nt < 4; nt++) {
            int col = wn * 32 + nt * 8 + 2 * t;
            atomicAdd(&cs[col], scol[nt * 2 + 0]);
            atomicAdd(&cs[col + 1], scol[nt * 2 + 1]);
            atomicAdd(&cq[col], qcol[nt * 2 + 0]);
            atomicAdd(&cq[col + 1], qcol[nt * 2 + 1]);
        }
    }
    __syncthreads();
    if (tid < 128) {
        atomicAdd(&psum[tid], ((const float*)(smem + SM_CSUM))[tid]);
        atomicAdd(&psq[tid], ((const float*)(smem + SM_CSQ))[tid]);
    }
}

// ---------------- finalize BN coefficients ----------------
__global__ void finalize_kernel(const float* __restrict__ s, const float* __restrict__ q,
                                const float* __restrict__ gam, const float* __restrict__ bet,
                                float* __restrict__ a, float* __restrict__ c, int N) {
    int j = threadIdx.x;
    float invN = 1.0f / (float)N;
    float mean = s[j] * invN;
    float var = fmaxf(q[j] * invN - mean * mean, 0.f);
    float rs = rsqrtf(var + 1e-5f);
    float aj = gam[j] * rs;
    a[j] = aj;
    c[j] = bet[j] - aj * mean;
}

// ---------------- final BN + leaky (in place) ----------------
__global__ void epilogue_kernel(float* __restrict__ Y, const float* __restrict__ a,
                                const float* __restrict__ c, int n4) {
    int i = blockIdx.x * blockDim.x + threadIdx.x;
    if (i < n4) {
        float4 v = ((const float4*)Y)[i];
        int cb = (i & 31) << 2;
        float t;
        t = a[cb + 0] * v.x + c[cb + 0]; v.x = leaky(t);
        t = a[cb + 1] * v.y + c[cb + 1]; v.y = leaky(t);
        t = a[cb + 2] * v.z + c[cb + 2]; v.z = leaky(t);
        t = a[cb + 3] * v.w + c[cb + 3]; v.w = leaky(t);
        ((float4*)Y)[i] = v;
    }
}

// ---------------- launch ----------------
extern "C" void kernel_launch(void* const* d_in, const int* in_sizes, int n_in,
                              void* d_out, int out_size) {
    const float* selfv = (const float*)d_in[0];
    const float* neigh = (const float*)d_in[1];
    const float* Wt    = (const float*)d_in[2];
    const float* aatt  = (const float*)d_in[3];
    const float* eps   = (const float*)d_in[4];
    const float* W1 = (const float*)d_in[5];
    const float* b1 = (const float*)d_in[6];
    const float* g1 = (const float*)d_in[7];
    const float* be1 = (const float*)d_in[8];
    const float* W2 = (const float*)d_in[9];
    const float* b2 = (const float*)d_in[10];
    const float* g2 = (const float*)d_in[11];
    const float* be2 = (const float*)d_in[12];
    const float* W3 = (const float*)d_in[13];
    const float* b3 = (const float*)d_in[14];
    const float* g3 = (const float*)d_in[15];
    const float* be3 = (const float*)d_in[16];
    float* out = (float*)d_out;

    int N = in_sizes[0] / 128;

    float *bufA = nullptr, *bufB = nullptr, *sum = nullptr, *sq = nullptr,
          *ca = nullptr, *cc = nullptr;
    __nv_bfloat16 *bthi = nullptr, *btlo = nullptr;
    cudaGetSymbolAddress((void**)&bufA, g_bufA);
    cudaGetSymbolAddress((void**)&bufB, g_bufB);
    cudaGetSymbolAddress((void**)&sum, g_sum);
    cudaGetSymbolAddress((void**)&sq, g_sq);
    cudaGetSymbolAddress((void**)&ca, g_ca);
    cudaGetSymbolAddress((void**)&cc, g_cc);
    cudaGetSymbolAddress((void**)&bthi, g_bthi);
    cudaGetSymbolAddress((void**)&btlo, g_btlo);

    cudaFuncSetAttribute(gemm_mma<false>, cudaFuncAttributeMaxDynamicSharedMemorySize, SM_TOTAL);
    cudaFuncSetAttribute(gemm_mma<true>, cudaFuncAttributeMaxDynamicSharedMemorySize, SM_TOTAL);

    prep_kernel<<<1, 256>>>(Wt, aatt);
    transpose_kernel<<<3, 256>>>(W1, W2, W3, bthi, btlo);
    attn_kernel<<<(N + 15) / 16, 256>>>(selfv, neigh, Wt, eps, bufA, N);

    int gg = (N + 127) / 128;
    gemm_mma<false><<<gg, 256, SM_TOTAL>>>(bufA, bthi + 0 * 16384, btlo + 0 * 16384, b1,
                                           nullptr, nullptr, bufB, sum + 0, sq + 0, N);
    finalize_kernel<<<1, 128>>>(sum + 0, sq + 0, g1, be1, ca + 0, cc + 0, N);

    gemm_mma<true><<<gg, 256, SM_TOTAL>>>(bufB, bthi + 1 * 16384, btlo + 1 * 16384, b2,
                                          ca + 0, cc + 0, bufA, sum + 128, sq + 128, N);
    finalize_kernel<<<1, 128>>>(sum + 128, sq + 128, g2, be2, ca + 128, cc + 128, N);

    gemm_mma<true><<<gg, 256, SM_TOTAL>>>(bufA, bthi + 2 * 16384, btlo + 2 * 16384, b3,
                                          ca + 128, cc + 128, out, sum + 256, sq + 256, N);
    finalize_kernel<<<1, 128>>>(sum + 256, sq + 256, g3, be3, ca + 256, cc + 256, N);

    int n4 = N * 32;
    epilogue_kernel<<<(n4 + 255) / 256, 256>>>(out, ca + 256, cc + 256, n4);
}

// round 5
// speedup vs baseline: 1.5842x; 1.4051x over previous
#include <cuda_runtime.h>
#include <cuda_bf16.h>
#include <cstdint>

#define ALPHA 0.2f
#define MAXN 50048

// ---------------- device scratch ----------------
__device__ float g_wself[128];
__device__ float g_wneigh[128];
__device__ float g_wc[16384];                // Wc = W_t @ W1  (fp32)
__device__ float g_bufA[MAXN * 128];
__device__ float g_bufB[MAXN * 128];
__device__ float g_sum[384];
__device__ float g_sq[384];
__device__ float g_ca[384];
__device__ float g_cc[384];
__device__ __nv_bfloat16 g_bthi[3 * 16384];  // B^T hi per layer, [n][k]
__device__ __nv_bfloat16 g_btlo[3 * 16384];  // B^T lo

__device__ __forceinline__ float leaky(float x) { return fmaxf(x, ALPHA * x); }

// ---------------- prep: attention vectors + zero stats ----------------
__global__ void prep_kernel(const float* __restrict__ Wt, const float* __restrict__ a_att) {
    int d = threadIdx.x;
    if (d < 128) {
        float s1 = 0.f, s2 = 0.f;
#pragma unroll 8
        for (int t = 0; t < 128; t++) {
            float w = Wt[d * 128 + t];
            s1 += w * a_att[t];
            s2 += w * a_att[128 + t];
        }
        g_wself[d] = s1;
        g_wneigh[d] = s2;
    }
    for (int i = threadIdx.x; i < 384; i += blockDim.x) {
        g_sum[i] = 0.f;
        g_sq[i] = 0.f;
    }
}

// ---------------- Wc = W_t @ W1 (128x128x128, fp32) ----------------
__global__ void wc_kernel(const float* __restrict__ Wt, const float* __restrict__ W1,
                          float* __restrict__ Wc) {
    int d = blockIdx.x;      // 128 blocks
    int h = threadIdx.x;     // 128 threads
    float acc = 0.f;
#pragma unroll 8
    for (int t = 0; t < 128; t++)
        acc += Wt[d * 128 + t] * W1[t * 128 + h];
    Wc[d * 128 + h] = acc;
}

// ---------------- transpose + hi/lo split of the 3 GEMM B matrices ----------------
__global__ void transpose_kernel(const float* __restrict__ Wc, const float* __restrict__ W2,
                                 const float* __restrict__ W3,
                                 __nv_bfloat16* __restrict__ bthi,
                                 __nv_bfloat16* __restrict__ btlo) {
    __shared__ float tile[32][33];
    const float* W = (blockIdx.x == 0) ? Wc : (blockIdx.x == 1) ? W2 : W3;
    __nv_bfloat16* oh = bthi + blockIdx.x * 16384;
    __nv_bfloat16* ol = btlo + blockIdx.x * 16384;
    int tx = threadIdx.x & 31, ty = threadIdx.x >> 5;  // 32 x 8
    for (int ti = 0; ti < 4; ti++)
        for (int tj = 0; tj < 4; tj++) {
            __syncthreads();
#pragma unroll
            for (int it = 0; it < 4; it++)
                tile[ty + 8 * it][tx] = W[(ti * 32 + ty + 8 * it) * 128 + tj * 32 + tx];
            __syncthreads();
#pragma unroll
            for (int it = 0; it < 4; it++) {
                int n = tj * 32 + ty + 8 * it, k = ti * 32 + tx;
                float v = tile[tx][ty + 8 * it];
                __nv_bfloat16 h = __float2bfloat16(v);
                oh[n * 128 + k] = h;
                ol[n * 128 + k] = __float2bfloat16(v - __bfloat162float(h));
            }
        }
}

// ---------------- attention: 1 warp = 1 node, register-resident neighbors ----------
// Loads all 25 neighbor float4s up front (MLP=25), batches the 26 dot-product
// reductions through pipelined butterfly shuffles, computes softmax per-lane
// (redundant, no serialization), then weighted-sums from registers.
// Output: x = (1+eps)*self + softmax-agg(neigh)  (D-space; W_t folded into GEMM1)
__global__ void __launch_bounds__(256)
attn_kernel(const float* __restrict__ selfv, const float* __restrict__ neigh,
            const float* __restrict__ eps_p, float* __restrict__ X, int N) {
    int tid = threadIdx.x;
    int wid = tid >> 5, l = tid & 31;
    int n = blockIdx.x * 8 + wid;
    int nn = (n < N) ? n : (N - 1);

    float onepe = 1.0f + eps_p[0];
    float4 ws4 = ((const float4*)g_wself)[l];
    float4 wn4 = ((const float4*)g_wneigh)[l];

    float4 sv = ((const float4*)(selfv + (long)nn * 128))[l];
    const float4* nb = (const float4*)(neigh + (long)nn * 3200);

    float4 v[25];
#pragma unroll
    for (int k = 0; k < 25; k++) v[k] = nb[k * 32 + l];

    float p[26];
    p[25] = sv.x * ws4.x + sv.y * ws4.y + sv.z * ws4.z + sv.w * ws4.w;
#pragma unroll
    for (int k = 0; k < 25; k++)
        p[k] = v[k].x * wn4.x + v[k].y * wn4.y + v[k].z * wn4.z + v[k].w * wn4.w;

#pragma unroll
    for (int o = 16; o > 0; o >>= 1)
#pragma unroll
        for (int k = 0; k < 26; k++) p[k] += __shfl_xor_sync(0xffffffffu, p[k], o);

    float ss = p[25];
    float m = -1e30f;
#pragma unroll
    for (int k = 0; k < 25; k++) {
        p[k] = leaky(p[k] + ss);
        m = fmaxf(m, p[k]);
    }
    float Z = 0.f;
#pragma unroll
    for (int k = 0; k < 25; k++) {
        p[k] = __expf(p[k] - m);
        Z += p[k];
    }
    float inv = 1.f / Z;

    float4 acc = make_float4(0.f, 0.f, 0.f, 0.f);
#pragma unroll
    for (int k = 0; k < 25; k++) {
        float w = p[k] * inv;
        acc.x += w * v[k].x;
        acc.y += w * v[k].y;
        acc.z += w * v[k].z;
        acc.w += w * v[k].w;
    }

    float4 x;
    x.x = onepe * sv.x + acc.x;
    x.y = onepe * sv.y + acc.y;
    x.z = onepe * sv.z + acc.z;
    x.w = onepe * sv.w + acc.w;
    if (n < N) ((float4*)(X + (long)n * 128))[l] = x;
}

// ---------------- mma.sync GEMM: Y = f(X) @ B^T + bias, fused BN stats ------------
#define A_STRIDE 272
#define SM_BIAS 0
#define SM_CSUM 512
#define SM_CSQ  1024
#define SM_AHI  1536
#define SM_ALO  (SM_AHI + 128 * A_STRIDE)
#define SM_BHI  (SM_ALO + 128 * A_STRIDE)
#define SM_BLO  (SM_BHI + 128 * A_STRIDE)
#define SM_TOTAL (SM_BLO + 128 * A_STRIDE)

__device__ __forceinline__ void mma16816(float* c, uint32_t a0, uint32_t a1, uint32_t a2,
                                         uint32_t a3, uint32_t b0, uint32_t b1) {
    asm volatile(
        "mma.sync.aligned.m16n8k16.row.col.f32.bf16.bf16.f32 "
        "{%0,%1,%2,%3}, {%4,%5,%6,%7}, {%8,%9}, {%0,%1,%2,%3};\n"
        : "+f"(c[0]), "+f"(c[1]), "+f"(c[2]), "+f"(c[3])
        : "r"(a0), "r"(a1), "r"(a2), "r"(a3), "r"(b0), "r"(b1));
}

template <bool HAS_IN>
__global__ void __launch_bounds__(256, 1)
gemm_mma(const float* __restrict__ X, const __nv_bfloat16* __restrict__ bthi,
         const __nv_bfloat16* __restrict__ btlo, const float* __restrict__ bias,
         const float* __restrict__ ain, const float* __restrict__ cin,
         float* __restrict__ Y, float* __restrict__ psum, float* __restrict__ psq,
         int N) {
    extern __shared__ char smem[];
    int tid = threadIdx.x;
    int wid = tid >> 5, lane = tid & 31;
    int wm = wid >> 2, wn = wid & 3;
    int g = lane >> 2, t = lane & 3;
    int row0 = blockIdx.x << 7;

    if (tid < 128) {
        ((float*)(smem + SM_BIAS))[tid] = bias[tid];
        ((float*)(smem + SM_CSUM))[tid] = 0.f;
        ((float*)(smem + SM_CSQ))[tid] = 0.f;
    }

#pragma unroll
    for (int it = 0; it < 16; it++) {
        int fi = tid + (it << 8);
        int r = fi >> 5, q = fi & 31;
        int gr = row0 + r;
        float4 v = make_float4(0.f, 0.f, 0.f, 0.f);
        if (gr < N) v = ((const float4*)X)[gr * 32 + q];
        if (HAS_IN) {
            int kk = q << 2;
            float tt;
            tt = ain[kk + 0] * v.x + cin[kk + 0]; v.x = leaky(tt);
            tt = ain[kk + 1] * v.y + cin[kk + 1]; v.y = leaky(tt);
            tt = ain[kk + 2] * v.z + cin[kk + 2]; v.z = leaky(tt);
            tt = ain[kk + 3] * v.w + cin[kk + 3]; v.w = leaky(tt);
        }
        __nv_bfloat162 h01, h23, l01, l23;
        h01.x = __float2bfloat16(v.x); h01.y = __float2bfloat16(v.y);
        h23.x = __float2bfloat16(v.z); h23.y = __float2bfloat16(v.w);
        l01.x = __float2bfloat16(v.x - __bfloat162float(h01.x));
        l01.y = __float2bfloat16(v.y - __bfloat162float(h01.y));
        l23.x = __float2bfloat16(v.z - __bfloat162float(h23.x));
        l23.y = __float2bfloat16(v.w - __bfloat162float(h23.y));
        int off = r * A_STRIDE + (q << 3);
        *(__nv_bfloat162*)(smem + SM_AHI + off) = h01;
        *(__nv_bfloat162*)(smem + SM_AHI + off + 4) = h23;
        *(__nv_bfloat162*)(smem + SM_ALO + off) = l01;
        *(__nv_bfloat162*)(smem + SM_ALO + off + 4) = l23;
    }

#pragma unroll
    for (int it = 0; it < 8; it++) {
        int fi = tid + (it << 8);
        int n = fi >> 4, c = fi & 15;
        uint4 vh = ((const uint4*)bthi)[fi];
        uint4 vl = ((const uint4*)btlo)[fi];
        int off = n * A_STRIDE + (c << 4);
        *(uint4*)(smem + SM_BHI + off) = vh;
        *(uint4*)(smem + SM_BLO + off) = vl;
    }
    __syncthreads();

    float acc[4][4][4];
#pragma unroll
    for (int mt = 0; mt < 4; mt++)
#pragma unroll
        for (int nt = 0; nt < 4; nt++)
#pragma unroll
            for (int j = 0; j < 4; j++) acc[mt][nt][j] = 0.f;

    const int abase0 = (wm * 64 + g) * A_STRIDE + t * 4;
    const int bbase0 = (wn * 32 + g) * A_STRIDE + t * 4;

#pragma unroll 1
    for (int s = 0; s < 3; s++) {
        const char* Ap = smem + (s == 2 ? SM_ALO : SM_AHI) + abase0;
        const char* Bp = smem + (s == 1 ? SM_BLO : SM_BHI) + bbase0;
#pragma unroll
        for (int ks = 0; ks < 8; ks++) {
            uint32_t a0[4], a1[4], a2[4], a3[4], b0[4], b1[4];
#pragma unroll
            for (int mt = 0; mt < 4; mt++) {
                const char* p = Ap + mt * 16 * A_STRIDE + ks * 32;
                a0[mt] = *(const uint32_t*)(p);
                a1[mt] = *(const uint32_t*)(p + 8 * A_STRIDE);
                a2[mt] = *(const uint32_t*)(p + 16);
                a3[mt] = *(const uint32_t*)(p + 8 * A_STRIDE + 16);
            }
#pragma unroll
            for (int nt = 0; nt < 4; nt++) {
                const char* p = Bp + nt * 8 * A_STRIDE + ks * 32;
                b0[nt] = *(const uint32_t*)(p);
                b1[nt] = *(const uint32_t*)(p + 16);
            }
#pragma unroll
            for (int mt = 0; mt < 4; mt++)
#pragma unroll
                for (int nt = 0; nt < 4; nt++)
                    mma16816(acc[mt][nt], a0[mt], a1[mt], a2[mt], a3[mt], b0[nt], b1[nt]);
        }
    }

    float scol[8], qcol[8];
#pragma unroll
    for (int j = 0; j < 8; j++) { scol[j] = 0.f; qcol[j] = 0.f; }

    const float* bs = (const float*)(smem + SM_BIAS);
#pragma unroll
    for (int nt = 0; nt < 4; nt++) {
        int col = wn * 32 + nt * 8 + 2 * t;
        float bv0 = bs[col], bv1 = bs[col + 1];
#pragma unroll
        for (int mt = 0; mt < 4; mt++) {
            int row = row0 + wm * 64 + mt * 16 + g;
            float c0 = acc[mt][nt][0] + bv0;
            float c1 = acc[mt][nt][1] + bv1;
            float c2 = acc[mt][nt][2] + bv0;
            float c3 = acc[mt][nt][3] + bv1;
            if (row < N) {
                *(float2*)(Y + (long)row * 128 + col) = make_float2(c0, c1);
                scol[nt * 2 + 0] += c0; qcol[nt * 2 + 0] += c0 * c0;
                scol[nt * 2 + 1] += c1; qcol[nt * 2 + 1] += c1 * c1;
            }
            if (row + 8 < N) {
                *(float2*)(Y + (long)(row + 8) * 128 + col) = make_float2(c2, c3);
                scol[nt * 2 + 0] += c2; qcol[nt * 2 + 0] += c2 * c2;
                scol[nt * 2 + 1] += c3; qcol[nt * 2 + 1] += c3 * c3;
            }
        }
    }
#pragma unroll
    for (int j = 0; j < 8; j++) {
#pragma unroll
        for (int o = 4; o < 32; o <<= 1) {
            scol[j] += __shfl_xor_sync(0xffffffffu, scol[j], o);
            qcol[j] += __shfl_xor_sync(0xffffffffu, qcol[j], o);
        }
    }
    if (g == 0) {
        float* cs = (float*)(smem + SM_CSUM);
        float* cq = (float*)(smem + SM_CSQ);
#pragma unroll
        for (int nt = 0; nt < 4; nt++) {
            int col = wn * 32 + nt * 8 + 2 * t;
            atomicAdd(&cs[col], scol[nt * 2 + 0]);
            atomicAdd(&cs[col + 1], scol[nt * 2 + 1]);
            atomicAdd(&cq[col], qcol[nt * 2 + 0]);
            atomicAdd(&cq[col + 1], qcol[nt * 2 + 1]);
        }
    }
    __syncthreads();
    if (tid < 128) {
        atomicAdd(&psum[tid], ((const float*)(smem + SM_CSUM))[tid]);
        atomicAdd(&psq[tid], ((const float*)(smem + SM_CSQ))[tid]);
    }
}

// ---------------- finalize BN coefficients ----------------
__global__ void finalize_kernel(const float* __restrict__ s, const float* __restrict__ q,
                                const float* __restrict__ gam, const float* __restrict__ bet,
                                float* __restrict__ a, float* __restrict__ c, int N) {
    int j = threadIdx.x;
    float invN = 1.0f / (float)N;
    float mean = s[j] * invN;
    float var = fmaxf(q[j] * invN - mean * mean, 0.f);
    float rs = rsqrtf(var + 1e-5f);
    float aj = gam[j] * rs;
    a[j] = aj;
    c[j] = bet[j] - aj * mean;
}

// ---------------- final BN + leaky (in place) ----------------
__global__ void epilogue_kernel(float* __restrict__ Y, const float* __restrict__ a,
                                const float* __restrict__ c, int n4) {
    int i = blockIdx.x * blockDim.x + threadIdx.x;
    if (i < n4) {
        float4 v = ((const float4*)Y)[i];
        int cb = (i & 31) << 2;
        float t;
        t = a[cb + 0] * v.x + c[cb + 0]; v.x = leaky(t);
        t = a[cb + 1] * v.y + c[cb + 1]; v.y = leaky(t);
        t = a[cb + 2] * v.z + c[cb + 2]; v.z = leaky(t);
        t = a[cb + 3] * v.w + c[cb + 3]; v.w = leaky(t);
        ((float4*)Y)[i] = v;
    }
}

// ---------------- launch ----------------
extern "C" void kernel_launch(void* const* d_in, const int* in_sizes, int n_in,
                              void* d_out, int out_size) {
    const float* selfv = (const float*)d_in[0];
    const float* neigh = (const float*)d_in[1];
    const float* Wt    = (const float*)d_in[2];
    const float* aatt  = (const float*)d_in[3];
    const float* eps   = (const float*)d_in[4];
    const float* W1 = (const float*)d_in[5];
    const float* b1 = (const float*)d_in[6];
    const float* g1 = (const float*)d_in[7];
    const float* be1 = (const float*)d_in[8];
    const float* W2 = (const float*)d_in[9];
    const float* b2 = (const float*)d_in[10];
    const float* g2 = (const float*)d_in[11];
    const float* be2 = (const float*)d_in[12];
    const float* W3 = (const float*)d_in[13];
    const float* b3 = (const float*)d_in[14];
    const float* g3 = (const float*)d_in[15];
    const float* be3 = (const float*)d_in[16];
    float* out = (float*)d_out;

    int N = in_sizes[0] / 128;

    float *bufA = nullptr, *bufB = nullptr, *sum = nullptr, *sq = nullptr,
          *ca = nullptr, *cc = nullptr, *wc = nullptr;
    __nv_bfloat16 *bthi = nullptr, *btlo = nullptr;
    cudaGetSymbolAddress((void**)&bufA, g_bufA);
    cudaGetSymbolAddress((void**)&bufB, g_bufB);
    cudaGetSymbolAddress((void**)&sum, g_sum);
    cudaGetSymbolAddress((void**)&sq, g_sq);
    cudaGetSymbolAddress((void**)&ca, g_ca);
    cudaGetSymbolAddress((void**)&cc, g_cc);
    cudaGetSymbolAddress((void**)&wc, g_wc);
    cudaGetSymbolAddress((void**)&bthi, g_bthi);
    cudaGetSymbolAddress((void**)&btlo, g_btlo);

    cudaFuncSetAttribute(gemm_mma<false>, cudaFuncAttributeMaxDynamicSharedMemorySize, SM_TOTAL);
    cudaFuncSetAttribute(gemm_mma<true>, cudaFuncAttributeMaxDynamicSharedMemorySize, SM_TOTAL);

    prep_kernel<<<1, 256>>>(Wt, aatt);
    wc_kernel<<<128, 128>>>(Wt, W1, wc);
    transpose_kernel<<<3, 256>>>(wc, W2, W3, bthi, btlo);
    attn_kernel<<<(N + 7) / 8, 256>>>(selfv, neigh, eps, bufA, N);

    int gg = (N + 127) / 128;
    gemm_mma<false><<<gg, 256, SM_TOTAL>>>(bufA, bthi + 0 * 16384, btlo + 0 * 16384, b1,
                                           nullptr, nullptr, bufB, sum + 0, sq + 0, N);
    finalize_kernel<<<1, 128>>>(sum + 0, sq + 0, g1, be1, ca + 0, cc + 0, N);

    gemm_mma<true><<<gg, 256, SM_TOTAL>>>(bufB, bthi + 1 * 16384, btlo + 1 * 16384, b2,
                                          ca + 0, cc + 0, bufA, sum + 128, sq + 128, N);
    finalize_kernel<<<1, 128>>>(sum + 128, sq + 128, g2, be2, ca + 128, cc + 128, N);

    gemm_mma<true><<<gg, 256, SM_TOTAL>>>(bufA, bthi + 2 * 16384, btlo + 2 * 16384, b3,
                                          ca + 128, cc + 128, out, sum + 256, sq + 256, N);
    finalize_kernel<<<1, 128>>>(sum + 256, sq + 256, g3, be3, ca + 256, cc + 256, N);

    int n4 = N * 32;
    epilogue_kernel<<<(n4 + 255) / 256, 256>>>(out, ca + 256, cc + 256, n4);
}